// round 7
// baseline (speedup 1.0000x reference)
#include <cuda_runtime.h>

// prob = sigmoid(x)*mask; sliding-window (W=30) mean; row max.
// B=2048, L=16384. Each block: 4 consecutive segments of 2048 starts,
// register-staged prefetch of segment k+1 issued before sliding segment k,
// double-buffered prob smem (1 barrier/segment). Combine via signed-int
// atomicMax (partials >= 0; poison 0xAAAAAAAA is negative as int).

#define ROW_L    16384
#define WIN      30
#define TPB      128
#define SEG      2048            // window starts per segment
#define SEGS_PB  4               // segments per block
#define NSUPER   2               // ROW_L / (SEG*SEGS_PB)
#define CHUNK    16              // starts per thread
#define COLS     130             // ≡ 2 (mod 32): conflict-free both phases
#define MAX_S    (ROW_L - WIN)   // 16354 = last valid start

__global__ __launch_bounds__(TPB, 8)
void win_max_pipe_kernel(const float* __restrict__ x,
                         const float* __restrict__ mask,
                         float* __restrict__ out)
{
    __shared__ float prob[2][16 * COLS];   // addr(i) = (i&15)*COLS + (i>>4)
    __shared__ float red[TPB / 32];

    const int sup = blockIdx.x;            // 0..1
    const int row = blockIdx.y;            // 0..2047
    const int tid = threadIdx.x;
    const size_t rbase = (size_t)row * ROW_L;
    const int base0 = sup * (SEG * SEGS_PB);

    const int c0 = (tid >> 2);             // convert column base (0..31)
    const int r0 = 4 * (tid & 3);          // convert row base

    // ---------------- register staging ----------------
    float4 rx0, rx1, rx2, rx3, rm0, rm1, rm2, rm3;
    float hx = 0.0f, hm = 0.0f;            // halo scalars (tid < 29)

    #define ISSUE(sbase_)                                                   \
    {                                                                       \
        const float4* x4_ = (const float4*)(x + rbase + (sbase_));          \
        const float4* m4_ = (const float4*)(mask + rbase + (sbase_));       \
        rx0 = __ldcs(&x4_[tid]);            rm0 = __ldcs(&m4_[tid]);        \
        rx1 = __ldcs(&x4_[tid + TPB]);      rm1 = __ldcs(&m4_[tid + TPB]);  \
        rx2 = __ldcs(&x4_[tid + 2 * TPB]);  rm2 = __ldcs(&m4_[tid + 2 * TPB]); \
        rx3 = __ldcs(&x4_[tid + 3 * TPB]);  rm3 = __ldcs(&m4_[tid + 3 * TPB]); \
        if (tid < WIN - 1) {                                                \
            const int gi_ = (sbase_) + SEG + tid;                           \
            if (gi_ < ROW_L) { hx = __ldcs(&x[rbase + gi_]);                \
                               hm = __ldcs(&mask[rbase + gi_]); }           \
            else             { hx = 0.0f; hm = 0.0f; }                      \
        }                                                                   \
    }

    #define CONV1(xv, mv, pb, m_)                                           \
    {                                                                       \
        const float p0_ = __fdividef((mv).x, 1.0f + __expf(-(xv).x));       \
        const float p1_ = __fdividef((mv).y, 1.0f + __expf(-(xv).y));       \
        const float p2_ = __fdividef((mv).z, 1.0f + __expf(-(xv).z));       \
        const float p3_ = __fdividef((mv).w, 1.0f + __expf(-(xv).w));       \
        const int cc_ = c0 + 32 * (m_);                                     \
        (pb)[(r0 + 0) * COLS + cc_] = p0_;                                  \
        (pb)[(r0 + 1) * COLS + cc_] = p1_;                                  \
        (pb)[(r0 + 2) * COLS + cc_] = p2_;                                  \
        (pb)[(r0 + 3) * COLS + cc_] = p3_;                                  \
    }

    float best = 0.0f;
    ISSUE(base0);

    #pragma unroll 1
    for (int k = 0; k < SEGS_PB; ++k) {
        const int sbase = base0 + k * SEG;
        float* pb = prob[k & 1];

        // ---- convert staged regs -> prob smem
        CONV1(rx0, rm0, pb, 0)
        CONV1(rx1, rm1, pb, 1)
        CONV1(rx2, rm2, pb, 2)
        CONV1(rx3, rm3, pb, 3)
        if (tid < WIN - 1) {
            const int il = SEG + tid;
            pb[(il & 15) * COLS + (il >> 4)] =
                __fdividef(hm, 1.0f + __expf(-hx));
        }

        // ---- prefetch next segment's raw data (in flight during slide)
        if (k + 1 < SEGS_PB) ISSUE(base0 + (k + 1) * SEG);

        __syncthreads();   // publish prob[k&1]

        // ---- sliding recurrence: 16 starts/thread from prob[k&1]
        float w = 0.0f;
        #pragma unroll
        for (int j = 0; j < WIN; ++j)
            w += pb[(j & 15) * COLS + tid + (j >> 4)];

        const int Sb = sbase + CHUNK * tid;
        if (Sb <= MAX_S) best = fmaxf(best, w);

        #pragma unroll
        for (int step = 1; step < CHUNK; ++step) {
            const int jin  = step + WIN - 1;   // 30..44
            const int jout = step - 1;         // 0..14
            w += pb[(jin & 15) * COLS + tid + (jin >> 4)]
               - pb[jout * COLS + tid];
            if (Sb + step <= MAX_S) best = fmaxf(best, w);
        }
        // no trailing barrier: slide(k) readers are separated from
        // convert(k+2) writers by the sync in iteration k+1.
    }

    // ---------------- block reduce + signed-int atomicMax
    #pragma unroll
    for (int off = 16; off > 0; off >>= 1)
        best = fmaxf(best, __shfl_xor_sync(0xFFFFFFFFu, best, off));
    if ((tid & 31) == 0) red[tid >> 5] = best;
    __syncthreads();
    if (tid == 0) {
        float b = red[0];
        #pragma unroll
        for (int i = 1; i < TPB / 32; ++i) b = fmaxf(b, red[i]);
        b *= (1.0f / (float)WIN);
        atomicMax((int*)&out[row], __float_as_int(b));
    }
}

extern "C" void kernel_launch(void* const* d_in, const int* in_sizes, int n_in,
                              void* d_out, int out_size)
{
    const float* x    = (const float*)d_in[0];
    const float* mask = (const float*)d_in[1];
    float* out = (float*)d_out;

    const int B = out_size;   // 2048 rows
    dim3 grid(NSUPER, B);
    win_max_pipe_kernel<<<grid, TPB>>>(x, mask, out);
}